// round 6
// baseline (speedup 1.0000x reference)
#include <cuda_runtime.h>
#include <cstdint>

#define Nn 200000
#define Ee 3200000
#define C  16
#define EPSV 1e-5f
#define SB  512
#define SBLK ((Nn + SB - 1) / SB)   // 391

// ---------------- scratch (no allocations allowed) ----------------
__device__ __align__(16) float g_dinv[Nn];     // rsqrt(deg+1)
__device__ __align__(16) float g_h[Nn * C];    // node features after linear
__device__ __align__(16) float g_agg[Nn * C];  // aggregation result
__device__ __align__(16) float g_stats[32];    // [0:16) sum, [16:32) sumsq
__device__ __align__(16) float g_bn[32];       // [0:16) scale, [16:32) shift
__device__ int  g_deg[Nn];                     // in-degree (edges only)
__device__ int  g_off[Nn];                     // CSR exclusive offsets
__device__ int  g_cur[Nn];                     // fill cursors
__device__ int  g_tmpI[Nn];                    // scan temp (inclusive)
__device__ int  g_bsum[SB];                    // block sums for scan
__device__ __align__(8) int2 g_csr[Ee];        // {src, __float_as_int(nrm)}

// ---------------- degree / CSR build ----------------
__global__ void k_deg_zero() {
    int i = blockIdx.x * blockDim.x + threadIdx.x;
    if (i < Nn) g_deg[i] = 0;
}

// edge_index is INT32 on device (harness converts int64 -> int32)
__global__ void k_deg_count(const int* __restrict__ ei) {
    int e = blockIdx.x * blockDim.x + threadIdx.x;
    if (e < Ee) {
        unsigned d = (unsigned)ei[Ee + e];
        if (d < Nn) atomicAdd(&g_deg[d], 1);   // clamp: garbage -> no crash
    }
}

__global__ void k_dinv() {
    int i = blockIdx.x * blockDim.x + threadIdx.x;
    if (i < Nn) g_dinv[i] = rsqrtf((float)(g_deg[i] + 1));  // +1 self-loop
}

// scan stage 1: per-block inclusive scan, record block totals
__global__ void k_scan1() {
    __shared__ int sm[SB];
    int t = threadIdx.x;
    int idx = blockIdx.x * SB + t;
    int v = (idx < Nn) ? g_deg[idx] : 0;
    sm[t] = v;
    __syncthreads();
    for (int o = 1; o < SB; o <<= 1) {
        int a = (t >= o) ? sm[t - o] : 0;
        __syncthreads();
        sm[t] += a;
        __syncthreads();
    }
    if (idx < Nn) g_tmpI[idx] = sm[t];
    if (t == SB - 1) g_bsum[blockIdx.x] = sm[t];
}

// scan stage 2: single-block exclusive scan of block sums
__global__ void k_scan2() {
    __shared__ int sm[SB];
    int t = threadIdx.x;
    int v = (t < SBLK) ? g_bsum[t] : 0;
    sm[t] = v;
    __syncthreads();
    for (int o = 1; o < SB; o <<= 1) {
        int a = (t >= o) ? sm[t - o] : 0;
        __syncthreads();
        sm[t] += a;
        __syncthreads();
    }
    if (t < SBLK) g_bsum[t] = sm[t] - v;  // exclusive
}

// scan stage 3: combine -> exclusive offsets + cursors
__global__ void k_scan3() {
    int idx = blockIdx.x * SB + threadIdx.x;
    if (idx < Nn) {
        int excl = g_tmpI[idx] - g_deg[idx] + g_bsum[blockIdx.x];
        g_off[idx] = excl;
        g_cur[idx] = excl;
    }
}

__global__ void k_fill(const int* __restrict__ ei) {
    int e = blockIdx.x * blockDim.x + threadIdx.x;
    if (e >= Ee) return;
    unsigned s = (unsigned)ei[e];
    unsigned d = (unsigned)ei[Ee + e];
    if (s >= Nn || d >= Nn) return;        // clamp: garbage -> no crash
    int slot = atomicAdd(&g_cur[d], 1);
    if ((unsigned)slot >= Ee) return;      // clamp
    float nrm = g_dinv[s] * g_dinv[d];
    g_csr[slot] = make_int2((int)s, __float_as_int(nrm));
}

// ---------------- layer 1 linear: g_h = x @ W1 ----------------
// warp per row; folding shuffle reduction (16 shfl instead of 80)
__global__ void k_lin1(const float* __restrict__ x, const float* __restrict__ W1) {
    __shared__ float Ws[256 * 16];
    int tid = threadIdx.x;
    for (int i = tid; i < 256 * 16; i += 256) Ws[i] = W1[i];
    __syncthreads();

    int warp = tid >> 5, lane = tid & 31;
    int row  = blockIdx.x * 8 + warp;
    if (row >= Nn) return;

    const float4* xp = (const float4*)(x + (size_t)row * 256);
    float4 xa = xp[lane];
    float4 xb = xp[32 + lane];

    float acc[16];
#pragma unroll
    for (int o = 0; o < 16; o++) acc[o] = 0.0f;

    {
        const float* xv = (const float*)&xa;
        int k0 = lane * 4;
#pragma unroll
        for (int j = 0; j < 4; j++) {
            float v = xv[j];
            const float* wr = &Ws[(k0 + j) * 16];
#pragma unroll
            for (int o = 0; o < 16; o++) acc[o] = fmaf(v, wr[o], acc[o]);
        }
    }
    {
        const float* xv = (const float*)&xb;
        int k0 = 128 + lane * 4;
#pragma unroll
        for (int j = 0; j < 4; j++) {
            float v = xv[j];
            const float* wr = &Ws[(k0 + j) * 16];
#pragma unroll
            for (int o = 0; o < 16; o++) acc[o] = fmaf(v, wr[o], acc[o]);
        }
    }

    const unsigned FULL = 0xffffffffu;
    float s8[8];
    {
        bool hi = (lane & 16) != 0;
#pragma unroll
        for (int o = 0; o < 8; o++) {
            float mine = hi ? acc[o + 8] : acc[o];
            float send = hi ? acc[o]     : acc[o + 8];
            s8[o] = mine + __shfl_xor_sync(FULL, send, 16);
        }
    }
    float s4[4];
    {
        bool hi = (lane & 8) != 0;
#pragma unroll
        for (int o = 0; o < 4; o++) {
            float mine = hi ? s8[o + 4] : s8[o];
            float send = hi ? s8[o]     : s8[o + 4];
            s4[o] = mine + __shfl_xor_sync(FULL, send, 8);
        }
    }
    float s2[2];
    {
        bool hi = (lane & 4) != 0;
#pragma unroll
        for (int o = 0; o < 2; o++) {
            float mine = hi ? s4[o + 2] : s4[o];
            float send = hi ? s4[o]     : s4[o + 2];
            s2[o] = mine + __shfl_xor_sync(FULL, send, 4);
        }
    }
    float s1;
    {
        bool hi = (lane & 2) != 0;
        float mine = hi ? s2[1] : s2[0];
        float send = hi ? s2[0] : s2[1];
        s1 = mine + __shfl_xor_sync(FULL, send, 2);
    }
    s1 += __shfl_xor_sync(FULL, s1, 1);

    int col = (((lane >> 4) & 1) << 3) | (((lane >> 3) & 1) << 2) |
              (((lane >> 2) & 1) << 1) | ((lane >> 1) & 1);
    if ((lane & 1) == 0) g_h[(size_t)row * 16 + col] = s1;
}

// ---------------- gather core: acc = dinv^2*h[node] + sum_e nrm*h[src] ----------------
__device__ __forceinline__ float4 gather_node(int node, int t) {
    int beg = g_off[node];
    int cnt = g_deg[node];
    if (beg < 0) beg = 0;
    if (cnt > Ee - beg) cnt = Ee - beg;    // clamp
    float di = g_dinv[node];
    float ss = di * di;

    const float4* h4 = (const float4*)g_h;
    float4 a = h4[(node << 2) + t];
    float4 acc;
    acc.x = ss * a.x; acc.y = ss * a.y; acc.z = ss * a.z; acc.w = ss * a.w;

#pragma unroll 2
    for (int i = 0; i < cnt; i++) {
        int2 r = g_csr[beg + i];
        float w = __int_as_float(r.y);
        unsigned sidx = (unsigned)r.x;
        if (sidx < Nn) {
            float4 v = h4[(sidx << 2) + t];
            acc.x = fmaf(w, v.x, acc.x);
            acc.y = fmaf(w, v.y, acc.y);
            acc.z = fmaf(w, v.z, acc.z);
            acc.w = fmaf(w, v.w, acc.w);
        }
    }
    return acc;
}

// 4 threads per node, each owns one float4 column slice
__global__ void k_gather_agg() {
    int gid  = blockIdx.x * blockDim.x + threadIdx.x;
    int node = gid >> 2;
    if (node >= Nn) return;
    int t = gid & 3;
    ((float4*)g_agg)[(node << 2) + t] = gather_node(node, t);
}

__global__ void k_gather_out(float* __restrict__ out, const float* __restrict__ bias) {
    int gid  = blockIdx.x * blockDim.x + threadIdx.x;
    int node = gid >> 2;
    if (node >= Nn) return;
    int t = gid & 3;
    float4 acc = gather_node(node, t);
    acc.x += bias[t * 4 + 0];
    acc.y += bias[t * 4 + 1];
    acc.z += bias[t * 4 + 2];
    acc.w += bias[t * 4 + 3];
    ((float4*)out)[(node << 2) + t] = acc;
}

// ---------------- BN stats ----------------
__global__ void k_zero_stats() {
    if (threadIdx.x < 32) g_stats[threadIdx.x] = 0.0f;
}

__global__ void k_bn_stats(const float* __restrict__ bvec) {
    int t   = blockIdx.x * blockDim.x + threadIdx.x;
    int nth = gridDim.x * blockDim.x;   // multiple of 16
    int col = t & 15;
    float b = bvec[col];
    float s = 0.0f, q = 0.0f;
    for (int idx = t; idx < Nn * C; idx += nth) {
        float v = g_agg[idx] + b;
        s += v;
        q = fmaf(v, v, q);
    }
    __shared__ float ss[16], sq[16];
    if (threadIdx.x < 16) { ss[threadIdx.x] = 0.0f; sq[threadIdx.x] = 0.0f; }
    __syncthreads();
    atomicAdd(&ss[col], s);
    atomicAdd(&sq[col], q);
    __syncthreads();
    if (threadIdx.x < 16) {
        atomicAdd(&g_stats[threadIdx.x], ss[threadIdx.x]);
        atomicAdd(&g_stats[16 + threadIdx.x], sq[threadIdx.x]);
    }
}

__global__ void k_bn_final(const float* __restrict__ gamma, const float* __restrict__ beta) {
    int t = threadIdx.x;
    if (t < 16) {
        float sum = g_stats[t], sq = g_stats[16 + t];
        float mu  = sum / (float)Nn;
        float var = sq / (float)Nn - mu * mu;
        float sc  = gamma[t] * rsqrtf(var + EPSV);
        g_bn[t]      = sc;
        g_bn[16 + t] = beta[t] - mu * sc;
    }
}

// ---------------- fused BN+ReLU+16x16 linear: g_h = relu(bn(g_agg+bprev)) @ W ----------------
__global__ void k_lin_mid(const float* __restrict__ W, const float* __restrict__ bprev) {
    __shared__ float Ws[256];
    __shared__ float sc_s[16], sh_s[16], bp_s[16];
    if (threadIdx.x < 256) Ws[threadIdx.x] = W[threadIdx.x];
    if (threadIdx.x < 16) {
        sc_s[threadIdx.x] = g_bn[threadIdx.x];
        sh_s[threadIdx.x] = g_bn[16 + threadIdx.x];
        bp_s[threadIdx.x] = bprev[threadIdx.x];
    }
    __syncthreads();

    int row = blockIdx.x * blockDim.x + threadIdx.x;
    if (row >= Nn) return;

    float z[16];
    const float4* ap = (const float4*)(g_agg + (size_t)row * 16);
#pragma unroll
    for (int j = 0; j < 4; j++) {
        float4 v = ap[j];
        const float* vv = (const float*)&v;
#pragma unroll
        for (int i = 0; i < 4; i++) {
            int k = j * 4 + i;
            float y = vv[i] + bp_s[k];
            z[k] = fmaxf(fmaf(sc_s[k], y, sh_s[k]), 0.0f);
        }
    }

    float o[16];
#pragma unroll
    for (int c = 0; c < 16; c++) o[c] = 0.0f;
#pragma unroll
    for (int k = 0; k < 16; k++) {
        float zk = z[k];
        const float* wr = &Ws[k * 16];
#pragma unroll
        for (int c = 0; c < 16; c++) o[c] = fmaf(zk, wr[c], o[c]);
    }

    float4* hv = (float4*)(g_h + (size_t)row * 16);
#pragma unroll
    for (int j = 0; j < 4; j++) {
        float4 hh;
        hh.x = o[j*4+0]; hh.y = o[j*4+1]; hh.z = o[j*4+2]; hh.w = o[j*4+3];
        hv[j] = hh;
    }
}

// ---------------- launch ----------------
extern "C" void kernel_launch(void* const* d_in, const int* in_sizes, int n_in,
                              void* d_out, int out_size) {
    // Identify inputs by SIZE (robust to metadata ordering):
    //   x: 51,200,000 f32 | edge_index: 6,400,000 INT32 (harness converts int64->int32)
    //   W1: 4096 | W2, W3: 256 (in order) | 16-elem: b1,g1,be1,b2,g2,be2,b3 (in order)
    const float* x  = nullptr;
    const int*   ei = nullptr;
    const float* W1 = nullptr;
    const float* W2 = nullptr;
    const float* W3 = nullptr;
    const float* v16[8] = {nullptr};
    int n16 = 0;
    for (int i = 0; i < n_in; i++) {
        int sz = in_sizes[i];
        if      (sz == 51200000) x  = (const float*)d_in[i];
        else if (sz == 6400000)  ei = (const int*)d_in[i];
        else if (sz == 4096)     W1 = (const float*)d_in[i];
        else if (sz == 256)      { if (!W2) W2 = (const float*)d_in[i]; else W3 = (const float*)d_in[i]; }
        else if (sz == 16 && n16 < 8) v16[n16++] = (const float*)d_in[i];
    }
    const float* b1  = v16[0];
    const float* g1  = v16[1];
    const float* be1 = v16[2];
    const float* b2  = v16[3];
    const float* g2  = v16[4];
    const float* be2 = v16[5];
    const float* b3  = v16[6];
    float* out = (float*)d_out;

    const int TB    = 256;
    const int nblk  = (Nn + TB - 1) / TB;
    const int eblk  = (Ee + TB - 1) / TB;
    const int l1blk = (Nn + 7) / 8;
    const int gblk  = (Nn * 4 + TB - 1) / TB;

    // ----- CSR build (once; shared by all 3 layers) -----
    k_deg_zero<<<nblk, TB>>>();
    k_deg_count<<<eblk, TB>>>(ei);
    k_dinv<<<nblk, TB>>>();
    k_scan1<<<SBLK, SB>>>();
    k_scan2<<<1, SB>>>();
    k_scan3<<<SBLK, SB>>>();
    k_fill<<<eblk, TB>>>(ei);

    // ----- layer 1 -----
    k_lin1<<<l1blk, TB>>>(x, W1);
    k_gather_agg<<<gblk, TB>>>();
    k_zero_stats<<<1, 32>>>();
    k_bn_stats<<<592, TB>>>(b1);
    k_bn_final<<<1, 16>>>(g1, be1);

    // ----- layer 2 -----
    k_lin_mid<<<nblk, TB>>>(W2, b1);
    k_gather_agg<<<gblk, TB>>>();
    k_zero_stats<<<1, 32>>>();
    k_bn_stats<<<592, TB>>>(b2);
    k_bn_final<<<1, 16>>>(g2, be2);

    // ----- layer 3 (gather writes d_out directly, +b3) -----
    k_lin_mid<<<nblk, TB>>>(W3, b2);
    k_gather_out<<<gblk, TB>>>(out, b3);
}

// round 7
// speedup vs baseline: 2.8853x; 2.8853x over previous
#include <cuda_runtime.h>
#include <cstdint>

#define Nn 200000
#define Ee 3200000
#define C  16
#define EPSV 1e-5f
#define SB  512
#define SBLK ((Nn + SB - 1) / SB)   // 391

// ---------------- scratch (no allocations allowed) ----------------
__device__ __align__(16) float g_dinv[Nn];     // rsqrt(deg+1)
__device__ __align__(16) float g_h[Nn * C];    // node features after linear
__device__ __align__(16) float g_agg[Nn * C];  // aggregation result
__device__ __align__(16) float g_stats[32];    // [0:16) sum, [16:32) sumsq
__device__ __align__(16) float g_bn[32];       // [0:16) scale, [16:32) shift
__device__ int  g_deg[Nn];                     // in-degree (edges only)
__device__ int  g_off[Nn];                     // CSR exclusive offsets
__device__ int  g_cur[Nn];                     // fill cursors
__device__ int  g_tmpI[Nn];                    // scan temp (inclusive)
__device__ int  g_bsum[SB];                    // block sums for scan
__device__ __align__(8) int2 g_csr[Ee];        // {src, __float_as_int(nrm)}

// ---------------- f32x2 packed math helpers ----------------
__device__ __forceinline__ unsigned long long pack2(float a, float b) {
    unsigned long long r;
    asm("mov.b64 %0, {%1, %2};" : "=l"(r) : "r"(__float_as_uint(a)), "r"(__float_as_uint(b)));
    return r;
}
__device__ __forceinline__ void unpack2(float& a, float& b, unsigned long long v) {
    unsigned lo, hi;
    asm("mov.b64 {%0, %1}, %2;" : "=r"(lo), "=r"(hi) : "l"(v));
    a = __uint_as_float(lo);
    b = __uint_as_float(hi);
}
__device__ __forceinline__ unsigned long long fma2(unsigned long long a, unsigned long long b,
                                                   unsigned long long c) {
    unsigned long long d;
    asm("fma.rn.f32x2 %0, %1, %2, %3;" : "=l"(d) : "l"(a), "l"(b), "l"(c));
    return d;
}

// ---------------- degree / CSR build ----------------
__global__ void k_deg_zero() {
    int i = blockIdx.x * blockDim.x + threadIdx.x;
    if (i < Nn) g_deg[i] = 0;
}

// edge_index is INT32 on device (harness converts int64 -> int32)
__global__ void k_deg_count(const int* __restrict__ ei) {
    int e = blockIdx.x * blockDim.x + threadIdx.x;
    if (e < Ee) {
        unsigned d = (unsigned)ei[Ee + e];
        if (d < Nn) atomicAdd(&g_deg[d], 1);
    }
}

__global__ void k_dinv() {
    int i = blockIdx.x * blockDim.x + threadIdx.x;
    if (i < Nn) g_dinv[i] = rsqrtf((float)(g_deg[i] + 1));  // +1 self-loop
}

__global__ void k_scan1() {
    __shared__ int sm[SB];
    int t = threadIdx.x;
    int idx = blockIdx.x * SB + t;
    int v = (idx < Nn) ? g_deg[idx] : 0;
    sm[t] = v;
    __syncthreads();
    for (int o = 1; o < SB; o <<= 1) {
        int a = (t >= o) ? sm[t - o] : 0;
        __syncthreads();
        sm[t] += a;
        __syncthreads();
    }
    if (idx < Nn) g_tmpI[idx] = sm[t];
    if (t == SB - 1) g_bsum[blockIdx.x] = sm[t];
}

__global__ void k_scan2() {
    __shared__ int sm[SB];
    int t = threadIdx.x;
    int v = (t < SBLK) ? g_bsum[t] : 0;
    sm[t] = v;
    __syncthreads();
    for (int o = 1; o < SB; o <<= 1) {
        int a = (t >= o) ? sm[t - o] : 0;
        __syncthreads();
        sm[t] += a;
        __syncthreads();
    }
    if (t < SBLK) g_bsum[t] = sm[t] - v;  // exclusive
}

__global__ void k_scan3() {
    int idx = blockIdx.x * SB + threadIdx.x;
    if (idx < Nn) {
        int excl = g_tmpI[idx] - g_deg[idx] + g_bsum[blockIdx.x];
        g_off[idx] = excl;
        g_cur[idx] = excl;
    }
}

__global__ void k_fill(const int* __restrict__ ei) {
    int e = blockIdx.x * blockDim.x + threadIdx.x;
    if (e >= Ee) return;
    unsigned s = (unsigned)ei[e];
    unsigned d = (unsigned)ei[Ee + e];
    if (s >= Nn || d >= Nn) return;
    int slot = atomicAdd(&g_cur[d], 1);
    if ((unsigned)slot >= Ee) return;
    float nrm = g_dinv[s] * g_dinv[d];
    g_csr[slot] = make_int2((int)s, __float_as_int(nrm));
}

// ---------------- layer 1 linear: g_h = x @ W1 ----------------
// warp handles 4 rows; lane l owns k in {l, l+32, ..., l+224}.
// W smem reads: per-lane row stride 64B -> 2-way bank conflict (vs 32-way before).
// Accumulators packed f32x2; folding shuffle reduce (62 SHFL per 4 rows).
__global__ void k_lin1(const float* __restrict__ x, const float* __restrict__ W1) {
    __shared__ __align__(16) float Ws[256 * 16];
    int tid = threadIdx.x;
#pragma unroll 4
    for (int i = tid; i < 256 * 16; i += 256) Ws[i] = W1[i];
    __syncthreads();

    int warp = tid >> 5, lane = tid & 31;
    int r0 = (blockIdx.x * 8 + warp) * 4;   // grid sized so r0+3 < Nn always

    unsigned long long acc2[32];            // [i*8 + o2]: rows i=0..3, col pairs o2=0..7
#pragma unroll
    for (int j = 0; j < 32; j++) acc2[j] = 0ULL;

#pragma unroll
    for (int s = 0; s < 8; s++) {
        int k = (s << 5) | lane;
        float x0 = x[(size_t)(r0 + 0) * 256 + k];
        float x1 = x[(size_t)(r0 + 1) * 256 + k];
        float x2 = x[(size_t)(r0 + 2) * 256 + k];
        float x3 = x[(size_t)(r0 + 3) * 256 + k];
        unsigned long long xp0 = pack2(x0, x0);
        unsigned long long xp1 = pack2(x1, x1);
        unsigned long long xp2 = pack2(x2, x2);
        unsigned long long xp3 = pack2(x3, x3);

        const ulonglong2* wp = (const ulonglong2*)(Ws + k * 16);
        ulonglong2 wq0 = wp[0], wq1 = wp[1], wq2 = wp[2], wq3 = wp[3];
        unsigned long long w2[8] = {wq0.x, wq0.y, wq1.x, wq1.y, wq2.x, wq2.y, wq3.x, wq3.y};

#pragma unroll
        for (int o2 = 0; o2 < 8; o2++) {
            acc2[0 * 8 + o2] = fma2(xp0, w2[o2], acc2[0 * 8 + o2]);
            acc2[1 * 8 + o2] = fma2(xp1, w2[o2], acc2[1 * 8 + o2]);
            acc2[2 * 8 + o2] = fma2(xp2, w2[o2], acc2[2 * 8 + o2]);
            acc2[3 * 8 + o2] = fma2(xp3, w2[o2], acc2[3 * 8 + o2]);
        }
    }

    // unpack to 64 scalars: vals[i*16 + o]
    float vals[64];
#pragma unroll
    for (int j = 0; j < 32; j++) unpack2(vals[2 * j], vals[2 * j + 1], acc2[j]);

    const unsigned FULL = 0xffffffffu;
    // folding reduce over 32 lanes: value msb absorbed into lane bit log2(mask)
#define FOLD_STAGE(n, m)                                                        \
    {                                                                           \
        bool hi = (lane & (m)) != 0;                                            \
        _Pragma("unroll")                                                       \
        for (int t = 0; t < (n) / 2; t++) {                                     \
            float mine = hi ? vals[t + (n) / 2] : vals[t];                      \
            float send = hi ? vals[t] : vals[t + (n) / 2];                      \
            vals[t] = mine + __shfl_xor_sync(FULL, send, (m));                  \
        }                                                                       \
    }
    FOLD_STAGE(64, 16)
    FOLD_STAGE(32, 8)
    FOLD_STAGE(16, 4)
    FOLD_STAGE(8, 2)
    FOLD_STAGE(4, 1)
#undef FOLD_STAGE

    // lane -> (row i, col o): i = lane[4:3], o = lane[2:0] << 1, plus vals[0]/vals[1]
    int i = (((lane >> 4) & 1) << 1) | ((lane >> 3) & 1);
    int o = (((lane >> 2) & 1) << 3) | (((lane >> 1) & 1) << 2) | ((lane & 1) << 1);
    int row = r0 + i;
    float2 st;
    st.x = vals[0];
    st.y = vals[1];
    ((float2*)g_h)[row * 8 + (o >> 1)] = st;
}

// ---------------- gather core: acc = dinv^2*h[node] + sum_e nrm*h[src] ----------------
__device__ __forceinline__ float4 gather_node(int node, int t) {
    int beg = g_off[node];
    int cnt = g_deg[node];
    if (beg < 0) beg = 0;
    if (cnt > Ee - beg) cnt = Ee - beg;
    float di = g_dinv[node];
    float ss = di * di;

    const float4* h4 = (const float4*)g_h;
    float4 a = h4[(node << 2) + t];
    float4 acc;
    acc.x = ss * a.x; acc.y = ss * a.y; acc.z = ss * a.z; acc.w = ss * a.w;

#pragma unroll 2
    for (int i = 0; i < cnt; i++) {
        int2 r = g_csr[beg + i];
        float w = __int_as_float(r.y);
        unsigned sidx = (unsigned)r.x;
        if (sidx < Nn) {
            float4 v = h4[(sidx << 2) + t];
            acc.x = fmaf(w, v.x, acc.x);
            acc.y = fmaf(w, v.y, acc.y);
            acc.z = fmaf(w, v.z, acc.z);
            acc.w = fmaf(w, v.w, acc.w);
        }
    }
    return acc;
}

__global__ void k_gather_agg() {
    int gid  = blockIdx.x * blockDim.x + threadIdx.x;
    int node = gid >> 2;
    if (node >= Nn) return;
    int t = gid & 3;
    ((float4*)g_agg)[(node << 2) + t] = gather_node(node, t);
}

__global__ void k_gather_out(float* __restrict__ out, const float* __restrict__ bias) {
    int gid  = blockIdx.x * blockDim.x + threadIdx.x;
    int node = gid >> 2;
    if (node >= Nn) return;
    int t = gid & 3;
    float4 acc = gather_node(node, t);
    acc.x += bias[t * 4 + 0];
    acc.y += bias[t * 4 + 1];
    acc.z += bias[t * 4 + 2];
    acc.w += bias[t * 4 + 3];
    ((float4*)out)[(node << 2) + t] = acc;
}

// ---------------- BN stats ----------------
__global__ void k_zero_stats() {
    if (threadIdx.x < 32) g_stats[threadIdx.x] = 0.0f;
}

__global__ void k_bn_stats(const float* __restrict__ bvec) {
    int t   = blockIdx.x * blockDim.x + threadIdx.x;
    int nth = gridDim.x * blockDim.x;
    int col = t & 15;
    float b = bvec[col];
    float s = 0.0f, q = 0.0f;
    for (int idx = t; idx < Nn * C; idx += nth) {
        float v = g_agg[idx] + b;
        s += v;
        q = fmaf(v, v, q);
    }
    __shared__ float ss[16], sq[16];
    if (threadIdx.x < 16) { ss[threadIdx.x] = 0.0f; sq[threadIdx.x] = 0.0f; }
    __syncthreads();
    atomicAdd(&ss[col], s);
    atomicAdd(&sq[col], q);
    __syncthreads();
    if (threadIdx.x < 16) {
        atomicAdd(&g_stats[threadIdx.x], ss[threadIdx.x]);
        atomicAdd(&g_stats[16 + threadIdx.x], sq[threadIdx.x]);
    }
}

__global__ void k_bn_final(const float* __restrict__ gamma, const float* __restrict__ beta) {
    int t = threadIdx.x;
    if (t < 16) {
        float sum = g_stats[t], sq = g_stats[16 + t];
        float mu  = sum / (float)Nn;
        float var = sq / (float)Nn - mu * mu;
        float sc  = gamma[t] * rsqrtf(var + EPSV);
        g_bn[t]      = sc;
        g_bn[16 + t] = beta[t] - mu * sc;
    }
}

// ---------------- fused BN+ReLU+16x16 linear: g_h = relu(bn(g_agg+bprev)) @ W ----------------
__global__ void k_lin_mid(const float* __restrict__ W, const float* __restrict__ bprev) {
    __shared__ float Ws[256];
    __shared__ float sc_s[16], sh_s[16], bp_s[16];
    if (threadIdx.x < 256) Ws[threadIdx.x] = W[threadIdx.x];
    if (threadIdx.x < 16) {
        sc_s[threadIdx.x] = g_bn[threadIdx.x];
        sh_s[threadIdx.x] = g_bn[16 + threadIdx.x];
        bp_s[threadIdx.x] = bprev[threadIdx.x];
    }
    __syncthreads();

    int row = blockIdx.x * blockDim.x + threadIdx.x;
    if (row >= Nn) return;

    float z[16];
    const float4* ap = (const float4*)(g_agg + (size_t)row * 16);
#pragma unroll
    for (int j = 0; j < 4; j++) {
        float4 v = ap[j];
        const float* vv = (const float*)&v;
#pragma unroll
        for (int i = 0; i < 4; i++) {
            int k = j * 4 + i;
            float y = vv[i] + bp_s[k];
            z[k] = fmaxf(fmaf(sc_s[k], y, sh_s[k]), 0.0f);
        }
    }

    float o[16];
#pragma unroll
    for (int c = 0; c < 16; c++) o[c] = 0.0f;
#pragma unroll
    for (int k = 0; k < 16; k++) {
        float zk = z[k];
        const float* wr = &Ws[k * 16];
#pragma unroll
        for (int c = 0; c < 16; c++) o[c] = fmaf(zk, wr[c], o[c]);
    }

    float4* hv = (float4*)(g_h + (size_t)row * 16);
#pragma unroll
    for (int j = 0; j < 4; j++) {
        float4 hh;
        hh.x = o[j*4+0]; hh.y = o[j*4+1]; hh.z = o[j*4+2]; hh.w = o[j*4+3];
        hv[j] = hh;
    }
}

// ---------------- launch ----------------
extern "C" void kernel_launch(void* const* d_in, const int* in_sizes, int n_in,
                              void* d_out, int out_size) {
    // Identify inputs by SIZE (robust to metadata ordering)
    const float* x  = nullptr;
    const int*   ei = nullptr;
    const float* W1 = nullptr;
    const float* W2 = nullptr;
    const float* W3 = nullptr;
    const float* v16[8] = {nullptr};
    int n16 = 0;
    for (int i = 0; i < n_in; i++) {
        int sz = in_sizes[i];
        if      (sz == 51200000) x  = (const float*)d_in[i];
        else if (sz == 6400000)  ei = (const int*)d_in[i];
        else if (sz == 4096)     W1 = (const float*)d_in[i];
        else if (sz == 256)      { if (!W2) W2 = (const float*)d_in[i]; else W3 = (const float*)d_in[i]; }
        else if (sz == 16 && n16 < 8) v16[n16++] = (const float*)d_in[i];
    }
    const float* b1  = v16[0];
    const float* g1  = v16[1];
    const float* be1 = v16[2];
    const float* b2  = v16[3];
    const float* g2  = v16[4];
    const float* be2 = v16[5];
    const float* b3  = v16[6];
    float* out = (float*)d_out;

    const int TB    = 256;
    const int nblk  = (Nn + TB - 1) / TB;
    const int eblk  = (Ee + TB - 1) / TB;
    const int l1blk = Nn / 32;              // 6250: 8 warps/block x 4 rows/warp, exact
    const int gblk  = (Nn * 4 + TB - 1) / TB;

    // ----- CSR build (once; shared by all 3 layers) -----
    k_deg_zero<<<nblk, TB>>>();
    k_deg_count<<<eblk, TB>>>(ei);
    k_dinv<<<nblk, TB>>>();
    k_scan1<<<SBLK, SB>>>();
    k_scan2<<<1, SB>>>();
    k_scan3<<<SBLK, SB>>>();
    k_fill<<<eblk, TB>>>(ei);

    // ----- layer 1 -----
    k_lin1<<<l1blk, TB>>>(x, W1);
    k_gather_agg<<<gblk, TB>>>();
    k_zero_stats<<<1, 32>>>();
    k_bn_stats<<<592, TB>>>(b1);
    k_bn_final<<<1, 16>>>(g1, be1);

    // ----- layer 2 -----
    k_lin_mid<<<nblk, TB>>>(W2, b1);
    k_gather_agg<<<gblk, TB>>>();
    k_zero_stats<<<1, 32>>>();
    k_bn_stats<<<592, TB>>>(b2);
    k_bn_final<<<1, 16>>>(g2, be2);

    // ----- layer 3 (gather writes d_out directly, +b3) -----
    k_lin_mid<<<nblk, TB>>>(W3, b2);
    k_gather_out<<<gblk, TB>>>(out, b3);
}

// round 8
// speedup vs baseline: 2.9628x; 1.0268x over previous
#include <cuda_runtime.h>
#include <cstdint>

#define Nn 200000
#define Ee 3200000
#define C  16
#define EPSV 1e-5f
#define SB  512
#define SBLK ((Nn + SB - 1) / SB)   // 391

// ---------------- scratch (no allocations allowed) ----------------
__device__ __align__(16) float g_dinv[Nn];     // rsqrt(deg+1)
__device__ __align__(16) float g_h[Nn * C];    // node features after linear
__device__ __align__(16) float g_agg[Nn * C];  // aggregation result (bias included)
__device__ __align__(16) float g_stats[64];    // layer1: [0:16) sum [16:32) sq; layer2: +32
__device__ int  g_deg[Nn];                     // in-degree (edges only)
__device__ int  g_off[Nn];                     // CSR exclusive offsets
__device__ int  g_cur[Nn];                     // fill cursors
__device__ int  g_tmpI[Nn];                    // scan temp (inclusive)
__device__ int  g_bsum[SB];                    // block sums for scan
__device__ __align__(16) int2 g_csr[Ee];       // {src, __float_as_int(nrm)}

// ---------------- f32x2 packed math helpers ----------------
__device__ __forceinline__ unsigned long long pack2(float a, float b) {
    unsigned long long r;
    asm("mov.b64 %0, {%1, %2};" : "=l"(r) : "r"(__float_as_uint(a)), "r"(__float_as_uint(b)));
    return r;
}
__device__ __forceinline__ void unpack2(float& a, float& b, unsigned long long v) {
    unsigned lo, hi;
    asm("mov.b64 {%0, %1}, %2;" : "=r"(lo), "=r"(hi) : "l"(v));
    a = __uint_as_float(lo);
    b = __uint_as_float(hi);
}
__device__ __forceinline__ unsigned long long fma2(unsigned long long a, unsigned long long b,
                                                   unsigned long long c) {
    unsigned long long d;
    asm("fma.rn.f32x2 %0, %1, %2, %3;" : "=l"(d) : "l"(a), "l"(b), "l"(c));
    return d;
}

// ---------------- init: zero degrees + zero both stats buffers ----------------
__global__ void k_init() {
    int i = blockIdx.x * blockDim.x + threadIdx.x;
    if (i < Nn) g_deg[i] = 0;
    if (blockIdx.x == 0 && threadIdx.x < 64) g_stats[threadIdx.x] = 0.0f;
}

// edge_index is INT32 on device (harness converts int64 -> int32)
__global__ void k_deg_count(const int* __restrict__ ei) {
    int e = blockIdx.x * blockDim.x + threadIdx.x;
    if (e < Ee) {
        unsigned d = (unsigned)ei[Ee + e];
        if (d < Nn) atomicAdd(&g_deg[d], 1);
    }
}

// scan stage 1 (+dinv fused): per-block inclusive scan, record block totals
__global__ void k_scan1() {
    __shared__ int sm[SB];
    int t = threadIdx.x;
    int idx = blockIdx.x * SB + t;
    int v = (idx < Nn) ? g_deg[idx] : 0;
    if (idx < Nn) g_dinv[idx] = rsqrtf((float)(v + 1));  // +1 self-loop
    sm[t] = v;
    __syncthreads();
    for (int o = 1; o < SB; o <<= 1) {
        int a = (t >= o) ? sm[t - o] : 0;
        __syncthreads();
        sm[t] += a;
        __syncthreads();
    }
    if (idx < Nn) g_tmpI[idx] = sm[t];
    if (t == SB - 1) g_bsum[blockIdx.x] = sm[t];
}

__global__ void k_scan2() {
    __shared__ int sm[SB];
    int t = threadIdx.x;
    int v = (t < SBLK) ? g_bsum[t] : 0;
    sm[t] = v;
    __syncthreads();
    for (int o = 1; o < SB; o <<= 1) {
        int a = (t >= o) ? sm[t - o] : 0;
        __syncthreads();
        sm[t] += a;
        __syncthreads();
    }
    if (t < SBLK) g_bsum[t] = sm[t] - v;  // exclusive
}

__global__ void k_scan3() {
    int idx = blockIdx.x * SB + threadIdx.x;
    if (idx < Nn) {
        int excl = g_tmpI[idx] - g_deg[idx] + g_bsum[blockIdx.x];
        g_off[idx] = excl;
        g_cur[idx] = excl;
    }
}

// fill writes EVERY claimed slot (invalid src -> {0, nrm=0}), so gather needs no guard
__global__ void k_fill(const int* __restrict__ ei) {
    int e = blockIdx.x * blockDim.x + threadIdx.x;
    if (e >= Ee) return;
    unsigned s = (unsigned)ei[e];
    unsigned d = (unsigned)ei[Ee + e];
    if (d >= Nn) return;                   // consistent with deg_count clamp
    int   ssrc = 0;
    float nrm  = 0.0f;
    if (s < Nn) { ssrc = (int)s; nrm = g_dinv[s] * g_dinv[d]; }
    int slot = atomicAdd(&g_cur[d], 1);
    g_csr[slot] = make_int2(ssrc, __float_as_int(nrm));
}

// ---------------- layer 1 linear: g_h = x @ W1 ----------------
// warp handles 4 rows; lane l owns k in {l, l+32, ...}; f32x2 accumulators.
__global__ void k_lin1(const float* __restrict__ x, const float* __restrict__ W1) {
    __shared__ __align__(16) float Ws[256 * 16];
    int tid = threadIdx.x;
#pragma unroll 4
    for (int i = tid; i < 256 * 16; i += 256) Ws[i] = W1[i];
    __syncthreads();

    int warp = tid >> 5, lane = tid & 31;
    int r0 = (blockIdx.x * 8 + warp) * 4;

    unsigned long long acc2[32];
#pragma unroll
    for (int j = 0; j < 32; j++) acc2[j] = 0ULL;

#pragma unroll
    for (int s = 0; s < 8; s++) {
        int k = (s << 5) | lane;
        float x0 = x[(size_t)(r0 + 0) * 256 + k];
        float x1 = x[(size_t)(r0 + 1) * 256 + k];
        float x2 = x[(size_t)(r0 + 2) * 256 + k];
        float x3 = x[(size_t)(r0 + 3) * 256 + k];
        unsigned long long xp0 = pack2(x0, x0);
        unsigned long long xp1 = pack2(x1, x1);
        unsigned long long xp2 = pack2(x2, x2);
        unsigned long long xp3 = pack2(x3, x3);

        const ulonglong2* wp = (const ulonglong2*)(Ws + k * 16);
        ulonglong2 wq0 = wp[0], wq1 = wp[1], wq2 = wp[2], wq3 = wp[3];
        unsigned long long w2[8] = {wq0.x, wq0.y, wq1.x, wq1.y, wq2.x, wq2.y, wq3.x, wq3.y};

#pragma unroll
        for (int o2 = 0; o2 < 8; o2++) {
            acc2[0 * 8 + o2] = fma2(xp0, w2[o2], acc2[0 * 8 + o2]);
            acc2[1 * 8 + o2] = fma2(xp1, w2[o2], acc2[1 * 8 + o2]);
            acc2[2 * 8 + o2] = fma2(xp2, w2[o2], acc2[2 * 8 + o2]);
            acc2[3 * 8 + o2] = fma2(xp3, w2[o2], acc2[3 * 8 + o2]);
        }
    }

    float vals[64];
#pragma unroll
    for (int j = 0; j < 32; j++) unpack2(vals[2 * j], vals[2 * j + 1], acc2[j]);

    const unsigned FULL = 0xffffffffu;
#define FOLD_STAGE(n, m)                                                        \
    {                                                                           \
        bool hi = (lane & (m)) != 0;                                            \
        _Pragma("unroll")                                                       \
        for (int t = 0; t < (n) / 2; t++) {                                     \
            float mine = hi ? vals[t + (n) / 2] : vals[t];                      \
            float send = hi ? vals[t] : vals[t + (n) / 2];                      \
            vals[t] = mine + __shfl_xor_sync(FULL, send, (m));                  \
        }                                                                       \
    }
    FOLD_STAGE(64, 16)
    FOLD_STAGE(32, 8)
    FOLD_STAGE(16, 4)
    FOLD_STAGE(8, 2)
    FOLD_STAGE(4, 1)
#undef FOLD_STAGE

    int i = (((lane >> 4) & 1) << 1) | ((lane >> 3) & 1);
    int o = (((lane >> 2) & 1) << 3) | (((lane >> 1) & 1) << 2) | ((lane & 1) << 1);
    int row = r0 + i;
    float2 st;
    st.x = vals[0];
    st.y = vals[1];
    ((float2*)g_h)[row * 8 + (o >> 1)] = st;
}

// ---------------- gather core: acc = dinv^2*h[node] + sum_e nrm*h[src] ----------------
// int4 double-record loads for 2x MLP on the record->feature chain.
__device__ __forceinline__ float4 gather_node(int node, int t) {
    int beg = g_off[node];
    int cnt = g_deg[node];
    int end = beg + cnt;
    float di = g_dinv[node];
    float ss = di * di;

    const float4* h4 = (const float4*)g_h;
    float4 a = h4[(node << 2) + t];
    float4 acc;
    acc.x = ss * a.x; acc.y = ss * a.y; acc.z = ss * a.z; acc.w = ss * a.w;

    int i = beg;
    if ((i & 1) && i < end) {
        int2 r = g_csr[i++];
        float w = __int_as_float(r.y);
        float4 v = h4[(r.x << 2) + t];
        acc.x = fmaf(w, v.x, acc.x);
        acc.y = fmaf(w, v.y, acc.y);
        acc.z = fmaf(w, v.z, acc.z);
        acc.w = fmaf(w, v.w, acc.w);
    }
    for (; i + 1 < end; i += 2) {
        int4 rr = *(const int4*)&g_csr[i];   // 2 records: {s0, n0, s1, n1}
        float w0 = __int_as_float(rr.y);
        float w1 = __int_as_float(rr.w);
        float4 v0 = h4[(rr.x << 2) + t];
        float4 v1 = h4[(rr.z << 2) + t];
        acc.x = fmaf(w0, v0.x, acc.x);
        acc.y = fmaf(w0, v0.y, acc.y);
        acc.z = fmaf(w0, v0.z, acc.z);
        acc.w = fmaf(w0, v0.w, acc.w);
        acc.x = fmaf(w1, v1.x, acc.x);
        acc.y = fmaf(w1, v1.y, acc.y);
        acc.z = fmaf(w1, v1.z, acc.z);
        acc.w = fmaf(w1, v1.w, acc.w);
    }
    if (i < end) {
        int2 r = g_csr[i];
        float w = __int_as_float(r.y);
        float4 v = h4[(r.x << 2) + t];
        acc.x = fmaf(w, v.x, acc.x);
        acc.y = fmaf(w, v.y, acc.y);
        acc.z = fmaf(w, v.z, acc.z);
        acc.w = fmaf(w, v.w, acc.w);
    }
    return acc;
}

// gather + bias + fused BN stats (sum/sumsq per column into g_stats[so..])
// grid is exact: 800000 threads = 3125 blocks x 256
__global__ void k_gather_agg(const float* __restrict__ bias, int so) {
    __shared__ float bsum[16], bsq[16];
    if (threadIdx.x < 16) { bsum[threadIdx.x] = 0.0f; bsq[threadIdx.x] = 0.0f; }
    __syncthreads();

    int gid  = blockIdx.x * blockDim.x + threadIdx.x;
    int node = gid >> 2;
    int t    = gid & 3;
    int lane = threadIdx.x & 31;

    float4 acc = gather_node(node, t);
    float4 b4  = ((const float4*)bias)[t];
    acc.x += b4.x; acc.y += b4.y; acc.z += b4.z; acc.w += b4.w;
    ((float4*)g_agg)[(node << 2) + t] = acc;

    // warp-level stats reduce: lanes with equal (lane&3)=t share column group
    float4 s1 = acc;
    float4 s2;
    s2.x = acc.x * acc.x; s2.y = acc.y * acc.y; s2.z = acc.z * acc.z; s2.w = acc.w * acc.w;
    const unsigned FULL = 0xffffffffu;
#pragma unroll
    for (int m = 4; m <= 16; m <<= 1) {
        s1.x += __shfl_xor_sync(FULL, s1.x, m);
        s1.y += __shfl_xor_sync(FULL, s1.y, m);
        s1.z += __shfl_xor_sync(FULL, s1.z, m);
        s1.w += __shfl_xor_sync(FULL, s1.w, m);
        s2.x += __shfl_xor_sync(FULL, s2.x, m);
        s2.y += __shfl_xor_sync(FULL, s2.y, m);
        s2.z += __shfl_xor_sync(FULL, s2.z, m);
        s2.w += __shfl_xor_sync(FULL, s2.w, m);
    }
    if (lane < 4) {
        atomicAdd(&bsum[t * 4 + 0], s1.x);
        atomicAdd(&bsum[t * 4 + 1], s1.y);
        atomicAdd(&bsum[t * 4 + 2], s1.z);
        atomicAdd(&bsum[t * 4 + 3], s1.w);
        atomicAdd(&bsq[t * 4 + 0], s2.x);
        atomicAdd(&bsq[t * 4 + 1], s2.y);
        atomicAdd(&bsq[t * 4 + 2], s2.z);
        atomicAdd(&bsq[t * 4 + 3], s2.w);
    }
    __syncthreads();
    if (threadIdx.x < 16) {
        atomicAdd(&g_stats[so + threadIdx.x], bsum[threadIdx.x]);
        atomicAdd(&g_stats[so + 16 + threadIdx.x], bsq[threadIdx.x]);
    }
}

__global__ void k_gather_out(float* __restrict__ out, const float* __restrict__ bias) {
    int gid  = blockIdx.x * blockDim.x + threadIdx.x;
    int node = gid >> 2;
    if (node >= Nn) return;
    int t = gid & 3;
    float4 acc = gather_node(node, t);
    float4 b4  = ((const float4*)bias)[t];
    acc.x += b4.x; acc.y += b4.y; acc.z += b4.z; acc.w += b4.w;
    ((float4*)out)[(node << 2) + t] = acc;
}

// ---------------- fused BNfinal+BN+ReLU+16x16 linear ----------------
// g_agg already contains (agg + bias); stats at g_stats[so..so+32)
__global__ void k_lin_mid(const float* __restrict__ W,
                          const float* __restrict__ gamma,
                          const float* __restrict__ beta, int so) {
    __shared__ float Ws[256];
    __shared__ float sc_s[16], sh_s[16];
    if (threadIdx.x < 256) Ws[threadIdx.x] = W[threadIdx.x];
    if (threadIdx.x < 16) {
        float sum = g_stats[so + threadIdx.x];
        float sq  = g_stats[so + 16 + threadIdx.x];
        float mu  = sum / (float)Nn;
        float var = sq / (float)Nn - mu * mu;
        float sc  = gamma[threadIdx.x] * rsqrtf(var + EPSV);
        sc_s[threadIdx.x] = sc;
        sh_s[threadIdx.x] = beta[threadIdx.x] - mu * sc;
    }
    __syncthreads();

    int row = blockIdx.x * blockDim.x + threadIdx.x;
    if (row >= Nn) return;

    float z[16];
    const float4* ap = (const float4*)(g_agg + (size_t)row * 16);
#pragma unroll
    for (int j = 0; j < 4; j++) {
        float4 v = ap[j];
        const float* vv = (const float*)&v;
#pragma unroll
        for (int i = 0; i < 4; i++) {
            int k = j * 4 + i;
            z[k] = fmaxf(fmaf(sc_s[k], vv[i], sh_s[k]), 0.0f);
        }
    }

    float o[16];
#pragma unroll
    for (int c = 0; c < 16; c++) o[c] = 0.0f;
#pragma unroll
    for (int k = 0; k < 16; k++) {
        float zk = z[k];
        const float* wr = &Ws[k * 16];
#pragma unroll
        for (int c = 0; c < 16; c++) o[c] = fmaf(zk, wr[c], o[c]);
    }

    float4* hv = (float4*)(g_h + (size_t)row * 16);
#pragma unroll
    for (int j = 0; j < 4; j++) {
        float4 hh;
        hh.x = o[j*4+0]; hh.y = o[j*4+1]; hh.z = o[j*4+2]; hh.w = o[j*4+3];
        hv[j] = hh;
    }
}

// ---------------- launch ----------------
extern "C" void kernel_launch(void* const* d_in, const int* in_sizes, int n_in,
                              void* d_out, int out_size) {
    // Identify inputs by SIZE (robust to metadata ordering)
    const float* x  = nullptr;
    const int*   ei = nullptr;
    const float* W1 = nullptr;
    const float* W2 = nullptr;
    const float* W3 = nullptr;
    const float* v16[8] = {nullptr};
    int n16 = 0;
    for (int i = 0; i < n_in; i++) {
        int sz = in_sizes[i];
        if      (sz == 51200000) x  = (const float*)d_in[i];
        else if (sz == 6400000)  ei = (const int*)d_in[i];
        else if (sz == 4096)     W1 = (const float*)d_in[i];
        else if (sz == 256)      { if (!W2) W2 = (const float*)d_in[i]; else W3 = (const float*)d_in[i]; }
        else if (sz == 16 && n16 < 8) v16[n16++] = (const float*)d_in[i];
    }
    const float* b1  = v16[0];
    const float* g1  = v16[1];
    const float* be1 = v16[2];
    const float* b2  = v16[3];
    const float* g2  = v16[4];
    const float* be2 = v16[5];
    const float* b3  = v16[6];
    float* out = (float*)d_out;

    const int TB    = 256;
    const int nblk  = (Nn + TB - 1) / TB;
    const int eblk  = (Ee + TB - 1) / TB;
    const int l1blk = Nn / 32;              // 6250
    const int gblk  = (Nn * 4) / TB;        // 3125 exact

    // ----- CSR build (once) -----
    k_init<<<nblk, TB>>>();
    k_deg_count<<<eblk, TB>>>(ei);
    k_scan1<<<SBLK, SB>>>();
    k_scan2<<<1, SB>>>();
    k_scan3<<<SBLK, SB>>>();
    k_fill<<<eblk, TB>>>(ei);

    // ----- layer 1 -----
    k_lin1<<<l1blk, TB>>>(x, W1);
    k_gather_agg<<<gblk, TB>>>(b1, 0);
    // ----- layer 2 -----
    k_lin_mid<<<nblk, TB>>>(W2, g1, be1, 0);
    k_gather_agg<<<gblk, TB>>>(b2, 32);
    // ----- layer 3 -----
    k_lin_mid<<<nblk, TB>>>(W3, g2, be2, 32);
    k_gather_out<<<gblk, TB>>>(out, b3);
}